// round 1
// baseline (speedup 1.0000x reference)
#include <cuda_runtime.h>
#include <cuda_bf16.h>
#include <math.h>

// Problem dims
#define TT 512   // time steps
#define BB 64    // batch
#define II 512   // input dim
#define HH 512   // hidden dim

// ---------------------------------------------------------------------------
// Scratch: double-buffered hidden state h[parity][b][k], 2*64*512 fp32 = 256KB
// ---------------------------------------------------------------------------
__device__ __align__(16) float g_hbuf[2 * BB * HH];

// Grid barrier state (persists across graph replays; generation-relative, safe)
__device__ unsigned g_bar_count = 0;
__device__ unsigned g_bar_gen   = 0;

__device__ __forceinline__ void grid_barrier(unsigned nblocks) {
    __syncthreads();
    if (threadIdx.x == 0) {
        __threadfence();                       // make this block's writes visible
        unsigned gen = *((volatile unsigned*)&g_bar_gen);  // MUST read before add
        __threadfence();
        unsigned ticket = atomicAdd(&g_bar_count, 1u);
        if (ticket == nblocks - 1) {
            atomicExch(&g_bar_count, 0u);      // reset before releasing
            __threadfence();
            *((volatile unsigned*)&g_bar_gen) = gen + 1u;
        } else {
            while (*((volatile unsigned*)&g_bar_gen) == gen) { __nanosleep(32); }
        }
        __threadfence();
    }
    __syncthreads();
}

// ---------------------------------------------------------------------------
// Phase 1: xp[m][n] = sum_k X[m][k] * W[n][k]   (M=T*B=32768, N=H=512, K=I=512)
// 128x128 block tile, BK=16, 8x8 per-thread micro-tile, 256 threads.
// Writes xp directly into the h_all region of d_out (overwritten in phase 2).
// ---------------------------------------------------------------------------
__global__ void __launch_bounds__(256) gemm_xp_kernel(
    const float* __restrict__ X, const float* __restrict__ W,
    float* __restrict__ C)
{
    const int K = II, N = HH;
    __shared__ __align__(16) float As[16][128];
    __shared__ __align__(16) float Bs[16][128];

    const int bm = blockIdx.x * 128;
    const int bn = blockIdx.y * 128;
    const int tid = threadIdx.x;
    const int tx = tid & 15;   // col group: cols tx*8 .. tx*8+7
    const int ty = tid >> 4;   // row group: rows ty*8 .. ty*8+7

    float acc[8][8];
#pragma unroll
    for (int i = 0; i < 8; i++)
#pragma unroll
        for (int j = 0; j < 8; j++) acc[i][j] = 0.0f;

    for (int k0 = 0; k0 < K; k0 += 16) {
        // Load A and B tiles: 128 rows x 16 cols each = 512 float4 each.
#pragma unroll
        for (int l = 0; l < 2; l++) {
            int idx = tid + l * 256;       // 0..511
            int r = idx >> 2;              // 0..127
            int c = (idx & 3) * 4;         // 0,4,8,12
            float4 va = *(const float4*)&X[(size_t)(bm + r) * K + k0 + c];
            As[c + 0][r] = va.x; As[c + 1][r] = va.y;
            As[c + 2][r] = va.z; As[c + 3][r] = va.w;
            float4 vb = *(const float4*)&W[(size_t)(bn + r) * K + k0 + c];
            Bs[c + 0][r] = vb.x; Bs[c + 1][r] = vb.y;
            Bs[c + 2][r] = vb.z; Bs[c + 3][r] = vb.w;
        }
        __syncthreads();

#pragma unroll
        for (int kk = 0; kk < 16; kk++) {
            float a[8], b[8];
            *(float4*)&a[0] = *(const float4*)&As[kk][ty * 8];
            *(float4*)&a[4] = *(const float4*)&As[kk][ty * 8 + 4];
            *(float4*)&b[0] = *(const float4*)&Bs[kk][tx * 8];
            *(float4*)&b[4] = *(const float4*)&Bs[kk][tx * 8 + 4];
#pragma unroll
            for (int i = 0; i < 8; i++)
#pragma unroll
                for (int j = 0; j < 8; j++)
                    acc[i][j] = fmaf(a[i], b[j], acc[i][j]);
        }
        __syncthreads();
    }

#pragma unroll
    for (int i = 0; i < 8; i++) {
        int row = bm + ty * 8 + i;
        float4 v0 = make_float4(acc[i][0], acc[i][1], acc[i][2], acc[i][3]);
        float4 v1 = make_float4(acc[i][4], acc[i][5], acc[i][6], acc[i][7]);
        *(float4*)&C[(size_t)row * N + bn + tx * 8]     = v0;
        *(float4*)&C[(size_t)row * N + bn + tx * 8 + 4] = v1;
    }
}

// ---------------------------------------------------------------------------
// Phase 2: persistent recurrence kernel.
// 128 blocks x 256 threads. Block bid owns output rows j in [bid*4, bid*4+4),
// whose W_hh rows live in SMEM for the whole kernel. Thread (jj, b) computes
// one output h[b][j] per step. h double-buffered in g_hbuf; cross-SM reads
// via __ldcg (L2) to dodge incoherent L1. One grid barrier per step.
// ---------------------------------------------------------------------------
#define NBLK 128

__global__ void __launch_bounds__(256) rnn_recurrence_kernel(
    const float* __restrict__ w_hh, float* __restrict__ out, int has_last)
{
    __shared__ __align__(16) float w_sh[4][HH];

    const int tid = threadIdx.x;
    const int bid = blockIdx.x;           // 0..127
    const int j0 = bid * 4;

    // Stage this block's 4 rows of W_hh into SMEM (stays resident all steps).
    for (int idx = tid; idx < 4 * HH; idx += 256) {
        int r = idx >> 9;         // 0..3
        int c = idx & (HH - 1);   // 0..511
        w_sh[r][c] = w_hh[(size_t)(j0 + r) * HH + c];
    }
    __syncthreads();

    const int b  = tid & 63;   // batch index (warp-contiguous)
    const int jj = tid >> 6;   // 0..3 (uniform within a warp -> LDS broadcast)
    const int j  = j0 + jj;

    float* __restrict__ hall  = out;                       // [T][B][H]
    float* __restrict__ hlast = out + (size_t)TT * BB * HH;
    const float4* __restrict__ w4 = (const float4*)&w_sh[jj][0];

    for (int t = 0; t < TT; t++) {
        // xp was written here by phase 1 (L1 flushed at launch boundary).
        float acc = hall[((size_t)t * BB + b) * HH + j];

        if (t > 0) {
            const int rbuf = (t & 1) ^ 1;   // buffer written at step t-1
            const float4* __restrict__ h4 =
                (const float4*)&g_hbuf[rbuf * BB * HH + b * HH];
            float a0 = 0.f, a1 = 0.f, a2 = 0.f, a3 = 0.f;
#pragma unroll 8
            for (int k = 0; k < HH / 4; k++) {
                float4 hv = __ldcg(&h4[k]);   // L2: peer-SM writes, skip L1
                float4 wv = w4[k];            // SMEM broadcast
                a0 = fmaf(hv.x, wv.x, a0);
                a1 = fmaf(hv.y, wv.y, a1);
                a2 = fmaf(hv.z, wv.z, a2);
                a3 = fmaf(hv.w, wv.w, a3);
            }
            acc += (a0 + a1) + (a2 + a3);
        }

        float h = tanhf(acc);

        hall[((size_t)t * BB + b) * HH + j] = h;          // h_all output
        g_hbuf[(t & 1) * BB * HH + b * HH + j] = h;       // next-step state
        if (has_last && t == TT - 1)
            hlast[b * HH + j] = h;                        // h_last output

        if (t != TT - 1) grid_barrier(NBLK);
    }
}

// ---------------------------------------------------------------------------
// Launch
// ---------------------------------------------------------------------------
extern "C" void kernel_launch(void* const* d_in, const int* in_sizes, int n_in,
                              void* d_out, int out_size) {
    const float* x    = (const float*)d_in[0];   // (T, B, I)
    const float* w_ih = (const float*)d_in[1];   // (H, I)
    const float* w_hh = (const float*)d_in[2];   // (H, H)
    float* out = (float*)d_out;

    // Phase 1: xp = x @ w_ih^T  into h_all region of out.
    dim3 g1((TT * BB) / 128, HH / 128);          // (256, 4)
    gemm_xp_kernel<<<g1, 256>>>(x, w_ih, out);

    // Phase 2: sequential recurrence, persistent kernel.
    int has_last = (out_size >= TT * BB * HH + BB * HH) ? 1 : 0;
    rnn_recurrence_kernel<<<NBLK, 256>>>(w_hh, out, has_last);
}

// round 2
// speedup vs baseline: 3.4418x; 3.4418x over previous
#include <cuda_runtime.h>
#include <cuda_bf16.h>
#include <math.h>

// Problem dims
#define TT 512   // time steps
#define BB 64    // batch
#define II 512   // input dim
#define HH 512   // hidden dim

#define NBLK 128           // phase-2 blocks (one wave)
#define JT 16              // j-cols per block
#define BT 16              // batches per block
#define PADW 4             // smem row pad (floats) -> stride 516
#define WSTR (HH + PADW)   // 516

// ---------------------------------------------------------------------------
// Scratch: double-buffered hidden state h[parity][b][k], 2*64*512 fp32 = 256KB
// ---------------------------------------------------------------------------
__device__ __align__(16) float g_hbuf[2 * BB * HH];

// Flag-array grid barrier (graph-replay safe via monotonic epoch)
__device__ __align__(16) unsigned g_arrive[NBLK];
__device__ unsigned g_epoch = 0;

// ---------------------------------------------------------------------------
// Phase 1: xp[m][n] = sum_k X[m][k] * W[n][k]   (M=T*B=32768, N=H=512, K=I=512)
// 128x128 block tile, BK=16, 8x8 per-thread micro-tile, 256 threads.
// Writes xp directly into the h_all region of d_out (overwritten in phase 2).
// ---------------------------------------------------------------------------
__global__ void __launch_bounds__(256) gemm_xp_kernel(
    const float* __restrict__ X, const float* __restrict__ W,
    float* __restrict__ C)
{
    const int K = II, N = HH;
    __shared__ __align__(16) float As[16][128];
    __shared__ __align__(16) float Bs[16][128];

    const int bm = blockIdx.x * 128;
    const int bn = blockIdx.y * 128;
    const int tid = threadIdx.x;
    const int tx = tid & 15;
    const int ty = tid >> 4;

    float acc[8][8];
#pragma unroll
    for (int i = 0; i < 8; i++)
#pragma unroll
        for (int j = 0; j < 8; j++) acc[i][j] = 0.0f;

    for (int k0 = 0; k0 < K; k0 += 16) {
#pragma unroll
        for (int l = 0; l < 2; l++) {
            int idx = tid + l * 256;
            int r = idx >> 2;
            int c = (idx & 3) * 4;
            float4 va = *(const float4*)&X[(size_t)(bm + r) * K + k0 + c];
            As[c + 0][r] = va.x; As[c + 1][r] = va.y;
            As[c + 2][r] = va.z; As[c + 3][r] = va.w;
            float4 vb = *(const float4*)&W[(size_t)(bn + r) * K + k0 + c];
            Bs[c + 0][r] = vb.x; Bs[c + 1][r] = vb.y;
            Bs[c + 2][r] = vb.z; Bs[c + 3][r] = vb.w;
        }
        __syncthreads();

#pragma unroll
        for (int kk = 0; kk < 16; kk++) {
            float a[8], b[8];
            *(float4*)&a[0] = *(const float4*)&As[kk][ty * 8];
            *(float4*)&a[4] = *(const float4*)&As[kk][ty * 8 + 4];
            *(float4*)&b[0] = *(const float4*)&Bs[kk][tx * 8];
            *(float4*)&b[4] = *(const float4*)&Bs[kk][tx * 8 + 4];
#pragma unroll
            for (int i = 0; i < 8; i++)
#pragma unroll
                for (int j = 0; j < 8; j++)
                    acc[i][j] = fmaf(a[i], b[j], acc[i][j]);
        }
        __syncthreads();
    }

#pragma unroll
    for (int i = 0; i < 8; i++) {
        int row = bm + ty * 8 + i;
        float4 v0 = make_float4(acc[i][0], acc[i][1], acc[i][2], acc[i][3]);
        float4 v1 = make_float4(acc[i][4], acc[i][5], acc[i][6], acc[i][7]);
        *(float4*)&C[(size_t)row * N + bn + tx * 8]     = v0;
        *(float4*)&C[(size_t)row * N + bn + tx * 8 + 4] = v1;
    }
}

// ---------------------------------------------------------------------------
// Phase 2: persistent recurrence.
// 128 blocks = 32 j-tiles x 4 b-tiles. Block owns JT=16 output cols and BT=16
// batches. W rows (16x512, padded) SMEM-resident for all steps. Each step:
//   - cooperative bulk __ldcg load of h-slice (BTx512 = 32KB) into SMEM
//   - thread (jj=tid&15, bb=tid>>4) computes one output via SMEM dot product
//   - flag-array grid barrier (monotonic targets, epoch-advanced per launch)
// ---------------------------------------------------------------------------
__global__ void __launch_bounds__(256) rnn_recurrence_kernel(
    const float* __restrict__ w_hh, float* __restrict__ out, int has_last)
{
    extern __shared__ __align__(16) float smem[];
    float* w_sh = smem;                    // [JT][WSTR]
    float* h_sh = smem + JT * WSTR;        // [BT][WSTR]

    const int tid = threadIdx.x;
    const int bid = blockIdx.x;
    const int j0 = (bid & 31) * JT;        // 32 j-tiles
    const int b0 = (bid >> 5) * BT;        // 4 b-tiles

    __shared__ unsigned s_epoch;
    if (tid == 0) s_epoch = *((volatile unsigned*)&g_epoch);

    // Stage W tile: w_sh[r][c] = w_hh[(j0+r)*HH + c]
    for (int idx = tid; idx < JT * (HH / 4); idx += 256) {
        int r = idx >> 7;            // 0..15  (128 float4 per row)
        int c4 = idx & 127;
        float4 v = *(const float4*)&w_hh[(size_t)(j0 + r) * HH + c4 * 4];
        *(float4*)&w_sh[r * WSTR + c4 * 4] = v;
    }
    __syncthreads();
    const unsigned epoch = s_epoch;

    const int jj = tid & 15;
    const int bb = tid >> 4;
    const int j = j0 + jj;
    const int b = b0 + bb;

    float* __restrict__ hall  = out;                       // [T][B][H]
    float* __restrict__ hlast = out + (size_t)TT * BB * HH;

    const float* __restrict__ wrow = &w_sh[jj * WSTR];
    const float* __restrict__ hrow = &h_sh[bb * WSTR];

    for (int t = 0; t < TT; t++) {
        // xp for this output (phase 1 wrote it here)
        float acc = hall[((size_t)t * BB + b) * HH + j];

        if (t > 0) {
            // Cooperative bulk load of h slice: rows b0..b0+15, contiguous.
            const int prev = (t - 1) & 1;
            const float4* __restrict__ src =
                (const float4*)&g_hbuf[prev * BB * HH + b0 * HH];
#pragma unroll
            for (int i = 0; i < 8; i++) {
                int idx = tid + i * 256;         // 0..2047
                float4 v = __ldcg(&src[idx]);
                int r = idx >> 7;                // 0..15
                int c4 = idx & 127;
                *(float4*)&h_sh[r * WSTR + c4 * 4] = v;
            }
            __syncthreads();

            float a0 = 0.f, a1 = 0.f, a2 = 0.f, a3 = 0.f;
#pragma unroll 8
            for (int k4 = 0; k4 < HH / 4; k4++) {
                float4 hv = *(const float4*)&hrow[k4 * 4];
                float4 wv = *(const float4*)&wrow[k4 * 4];
                a0 = fmaf(hv.x, wv.x, a0);
                a1 = fmaf(hv.y, wv.y, a1);
                a2 = fmaf(hv.z, wv.z, a2);
                a3 = fmaf(hv.w, wv.w, a3);
            }
            acc += (a0 + a1) + (a2 + a3);
        }

        float h = tanhf(acc);

        hall[((size_t)t * BB + b) * HH + j] = h;           // h_all
        g_hbuf[(t & 1) * BB * HH + (size_t)b * HH + j] = h; // state
        if (has_last && t == TT - 1)
            hlast[(size_t)b * HH + j] = h;                  // h_last

        if (t != TT - 1) {
            // ---- flag-array grid barrier ----
            __syncthreads();   // all stores of this block issued + h_sh free
            if (tid < 32) {
                const unsigned target = epoch + (unsigned)t + 1u;
                if (tid == 0) {
                    __threadfence();
                    *((volatile unsigned*)&g_arrive[bid]) = target;
                }
                const uint4* f4 = (const uint4*)g_arrive;
                for (;;) {
                    uint4 v = __ldcg(&f4[tid]);   // 32 lanes x 4 = 128 flags
                    bool ok = (v.x >= target) & (v.y >= target) &
                              (v.z >= target) & (v.w >= target);
                    if (__all_sync(0xffffffffu, ok)) break;
                    __nanosleep(64);
                }
                __threadfence();
            }
            __syncthreads();
        }
    }

    // Advance epoch for the next graph replay (stream order guarantees the
    // next launch reads this only after this kernel fully completes).
    if (bid == 0 && tid == 0)
        *((volatile unsigned*)&g_epoch) = epoch + (unsigned)TT;
}

// ---------------------------------------------------------------------------
// Launch
// ---------------------------------------------------------------------------
extern "C" void kernel_launch(void* const* d_in, const int* in_sizes, int n_in,
                              void* d_out, int out_size) {
    const float* x    = (const float*)d_in[0];   // (T, B, I)
    const float* w_ih = (const float*)d_in[1];   // (H, I)
    const float* w_hh = (const float*)d_in[2];   // (H, H)
    float* out = (float*)d_out;

    // Phase 1: xp = x @ w_ih^T into h_all region of out.
    dim3 g1((TT * BB) / 128, HH / 128);          // (256, 4)
    gemm_xp_kernel<<<g1, 256>>>(x, w_ih, out);

    // Phase 2: persistent recurrence.
    int smem_bytes = (JT + BT) * WSTR * sizeof(float);   // ~66KB
    cudaFuncSetAttribute(rnn_recurrence_kernel,
                         cudaFuncAttributeMaxDynamicSharedMemorySize, smem_bytes);
    int has_last = (out_size >= TT * BB * HH + BB * HH) ? 1 : 0;
    rnn_recurrence_kernel<<<NBLK, 256, smem_bytes>>>(w_hh, out, has_last);
}

// round 3
// speedup vs baseline: 4.7660x; 1.3847x over previous
#include <cuda_runtime.h>
#include <cuda_bf16.h>
#include <math.h>

// Problem dims
#define TT 512
#define BB 64
#define II 512
#define HH 512

// Phase-2 tiling: 128 blocks = 8 groups (8 batches each) x 16 j-tiles (32 j).
#define NBLK 128
#define GRPS 8           // groups (b-slices)
#define GBLK 16          // blocks per group (j-tiles)
#define JT   32          // j per block
#define BT   8           // b per block (= per group)
#define KS   4           // split-k factor
// smem float4 strides
#define WS4  36          // w_sh: [128 k4][36] float4 (32 rows + 4 pad)
#define HS4  8           // h_sh: [128 k4][8] float4

// ---------------------------------------------------------------------------
__device__ __align__(16) float g_hbuf[2 * BB * HH];
__device__ __align__(16) unsigned g_arrive[NBLK];   // zero-init; monotonic

// ---------------------------------------------------------------------------
// Phase 1: xp = X @ W^T  (M=32768, N=512, K=512), 128x128 tile, 8x8 micro.
// ---------------------------------------------------------------------------
__global__ void __launch_bounds__(256) gemm_xp_kernel(
    const float* __restrict__ X, const float* __restrict__ W,
    float* __restrict__ C)
{
    const int K = II, N = HH;
    __shared__ __align__(16) float As[16][128];
    __shared__ __align__(16) float Bs[16][128];

    const int bm = blockIdx.x * 128;
    const int bn = blockIdx.y * 128;
    const int tid = threadIdx.x;
    const int tx = tid & 15;
    const int ty = tid >> 4;

    float acc[8][8];
#pragma unroll
    for (int i = 0; i < 8; i++)
#pragma unroll
        for (int j = 0; j < 8; j++) acc[i][j] = 0.0f;

    for (int k0 = 0; k0 < K; k0 += 16) {
#pragma unroll
        for (int l = 0; l < 2; l++) {
            int idx = tid + l * 256;
            int r = idx >> 2;
            int c = (idx & 3) * 4;
            float4 va = *(const float4*)&X[(size_t)(bm + r) * K + k0 + c];
            As[c + 0][r] = va.x; As[c + 1][r] = va.y;
            As[c + 2][r] = va.z; As[c + 3][r] = va.w;
            float4 vb = *(const float4*)&W[(size_t)(bn + r) * K + k0 + c];
            Bs[c + 0][r] = vb.x; Bs[c + 1][r] = vb.y;
            Bs[c + 2][r] = vb.z; Bs[c + 3][r] = vb.w;
        }
        __syncthreads();

#pragma unroll
        for (int kk = 0; kk < 16; kk++) {
            float a[8], b[8];
            *(float4*)&a[0] = *(const float4*)&As[kk][ty * 8];
            *(float4*)&a[4] = *(const float4*)&As[kk][ty * 8 + 4];
            *(float4*)&b[0] = *(const float4*)&Bs[kk][tx * 8];
            *(float4*)&b[4] = *(const float4*)&Bs[kk][tx * 8 + 4];
#pragma unroll
            for (int i = 0; i < 8; i++)
#pragma unroll
                for (int j = 0; j < 8; j++)
                    acc[i][j] = fmaf(a[i], b[j], acc[i][j]);
        }
        __syncthreads();
    }

#pragma unroll
    for (int i = 0; i < 8; i++) {
        int row = bm + ty * 8 + i;
        float4 v0 = make_float4(acc[i][0], acc[i][1], acc[i][2], acc[i][3]);
        float4 v1 = make_float4(acc[i][4], acc[i][5], acc[i][6], acc[i][7]);
        *(float4*)&C[(size_t)row * N + bn + tx * 8]     = v0;
        *(float4*)&C[(size_t)row * N + bn + tx * 8 + 4] = v1;
    }
}

// ---------------------------------------------------------------------------
// Phase 2: persistent recurrence, group barriers + split-k register tiling.
//   bid = g*16 + jt;  b0 = g*8, j0 = jt*32.
//   thread: ks = tid>>6, jh = (tid>>5)&1, bp = (tid>>3)&3, jl = tid&7,
//           jp = jh*8+jl. Computes c[2][2] for j={2jp,2jp+1}, b={2bp,2bp+1}
//           over k in [ks*128, ks*128+128). Partials reduced via smem.
// ---------------------------------------------------------------------------
__global__ void __launch_bounds__(256) rnn_recurrence_kernel(
    const float* __restrict__ w_hh, float* __restrict__ out, int has_last)
{
    extern __shared__ __align__(16) float smem[];
    float4* w_sh4 = (float4*)smem;                       // [128][WS4]
    float4* h_sh4 = w_sh4 + 128 * WS4;                   // [128][HS4]
    float*  red   = (float*)(h_sh4 + 128 * HS4);         // [KS][256]

    const int tid = threadIdx.x;
    const int bid = blockIdx.x;
    const int grp = bid >> 4;          // 0..7
    const int jt  = bid & 15;          // 0..15
    const int b0  = grp * BT;
    const int j0  = jt * JT;

    // Epoch base = own flag's previous value (uniform across blocks).
    __shared__ unsigned s_base;
    if (tid == 0) s_base = *((volatile unsigned*)&g_arrive[bid]);

    // Stage W tile transposed: w_sh4[k4*WS4 + row] = w_hh[(j0+row)][4k4..]
    {
        const float4* wsrc = (const float4*)w_hh;
#pragma unroll
        for (int r = 0; r < 16; r++) {
            int idx = tid + r * 256;           // 0..4095
            int row = idx >> 7;                // 0..31
            int k4  = idx & 127;
            w_sh4[k4 * WS4 + row] = wsrc[(size_t)(j0 + row) * 128 + k4];
        }
    }
    __syncthreads();
    const unsigned base = s_base;

    const int ks = tid >> 6;
    const int jp = ((tid >> 5) & 1) * 8 + (tid & 7);
    const int bp = (tid >> 3) & 3;

    // output mapping for reduction/IO phase
    const int oj = tid & 31;       // j within tile
    const int ob = tid >> 5;       // b within tile
    const int gj = j0 + oj;
    const int gb = b0 + ob;

    float* __restrict__ hall  = out;
    float* __restrict__ hlast = out + (size_t)TT * BB * HH;

    const float4* __restrict__ hb4 = (const float4*)g_hbuf;

    for (int t = 0; t < TT; t++) {
        // Prefetch xp (own slice of hall[t], no cross-block hazard).
        float xp = hall[((size_t)t * BB + gb) * HH + gj];

        float hsum = 0.0f;
        if (t > 0) {
            // ---- group barrier: wait all 16 group blocks signaled step t-1
            if (tid < 32) {
                const unsigned tgt = base + (unsigned)t;   // signals are base+1+t'
                const uint4* f4 = (const uint4*)g_arrive;
                int fi = grp * 4 + (tid & 3);
                for (;;) {
                    uint4 v = __ldcg(&f4[fi]);
                    bool ok = (v.x >= tgt) & (v.y >= tgt) &
                              (v.z >= tgt) & (v.w >= tgt);
                    if (__all_sync(0xffffffffu, ok)) break;
                    __nanosleep(32);
                }
                __threadfence();
            }
            __syncthreads();

            // ---- bulk load h(t-1) slice [8 b][512 k] -> h_sh4[k4][b]
            const int prev = (t - 1) & 1;
            const float4* src = hb4 + (size_t)prev * (BB * HH / 4)
                                    + (size_t)b0 * 128;
#pragma unroll
            for (int r = 0; r < 4; r++) {
                int idx = tid + r * 256;       // 0..1023
                int b = idx >> 7;              // 0..7
                int k4 = idx & 127;
                float4 v = __ldcg(&src[(size_t)b * 128 + k4]);
                h_sh4[k4 * HS4 + b] = v;
            }
            __syncthreads();

            // ---- compute partial c[2][2] over this thread's k-range
            float c00 = 0.f, c01 = 0.f, c10 = 0.f, c11 = 0.f;
            const float4* wp = w_sh4 + (size_t)(ks * 32) * WS4 + 2 * jp;
            const float4* hp = h_sh4 + (size_t)(ks * 32) * HS4 + 2 * bp;
#pragma unroll 8
            for (int k4 = 0; k4 < 32; k4++) {
                float4 w0 = wp[0];
                float4 w1 = wp[1];
                float4 h0 = hp[0];
                float4 h1 = hp[1];
                c00 = fmaf(w0.x, h0.x, c00); c00 = fmaf(w0.y, h0.y, c00);
                c00 = fmaf(w0.z, h0.z, c00); c00 = fmaf(w0.w, h0.w, c00);
                c01 = fmaf(w0.x, h1.x, c01); c01 = fmaf(w0.y, h1.y, c01);
                c01 = fmaf(w0.z, h1.z, c01); c01 = fmaf(w0.w, h1.w, c01);
                c10 = fmaf(w1.x, h0.x, c10); c10 = fmaf(w1.y, h0.y, c10);
                c10 = fmaf(w1.z, h0.z, c10); c10 = fmaf(w1.w, h0.w, c10);
                c11 = fmaf(w1.x, h1.x, c11); c11 = fmaf(w1.y, h1.y, c11);
                c11 = fmaf(w1.z, h1.z, c11); c11 = fmaf(w1.w, h1.w, c11);
                wp += WS4;
                hp += HS4;
            }

            // ---- store partials: red[ks][(2bp+ii)*32 + 2jp+i]
            {
                float* rr = red + ks * 256;
                rr[(2 * bp + 0) * 32 + 2 * jp + 0] = c00;
                rr[(2 * bp + 1) * 32 + 2 * jp + 0] = c01;
                rr[(2 * bp + 0) * 32 + 2 * jp + 1] = c10;
                rr[(2 * bp + 1) * 32 + 2 * jp + 1] = c11;
            }
            __syncthreads();

            hsum = red[0 * 256 + tid] + red[1 * 256 + tid]
                 + red[2 * 256 + tid] + red[3 * 256 + tid];
        }

        float h = tanhf(xp + hsum);

        // outputs
        hall[((size_t)t * BB + gb) * HH + gj] = h;
        g_hbuf[((size_t)(t & 1) * BB + gb) * HH + gj] = h;
        if (has_last && t == TT - 1)
            hlast[(size_t)gb * HH + gj] = h;

        if (t != TT - 1) {
            __syncthreads();               // all stores issued; red/h_sh free
            if (tid == 0) {
                __threadfence();
                *((volatile unsigned*)&g_arrive[bid]) = base + 1u + (unsigned)t;
            }
            // (next iteration's barrier wait provides the sync)
        }
    }
}

// ---------------------------------------------------------------------------
extern "C" void kernel_launch(void* const* d_in, const int* in_sizes, int n_in,
                              void* d_out, int out_size) {
    const float* x    = (const float*)d_in[0];   // (T, B, I)
    const float* w_ih = (const float*)d_in[1];   // (H, I)
    const float* w_hh = (const float*)d_in[2];   // (H, H)
    float* out = (float*)d_out;

    dim3 g1((TT * BB) / 128, HH / 128);
    gemm_xp_kernel<<<g1, 256>>>(x, w_ih, out);

    int smem_bytes = (128 * WS4 + 128 * HS4) * 16 + KS * 256 * 4;  // ~94KB
    cudaFuncSetAttribute(rnn_recurrence_kernel,
                         cudaFuncAttributeMaxDynamicSharedMemorySize, smem_bytes);
    int has_last = (out_size >= TT * BB * HH + BB * HH) ? 1 : 0;
    rnn_recurrence_kernel<<<NBLK, 256, smem_bytes>>>(w_hh, out, has_last);
}

// round 5
// speedup vs baseline: 8.5101x; 1.7856x over previous
#include <cuda_runtime.h>
#include <cuda_bf16.h>
#include <math.h>

// Problem dims
#define TT 512
#define BB 64
#define II 512
#define HH 512

// Phase-2: 128 blocks = 8 groups (8 batches) x 16 j-tiles (32 j each).
#define NBLK 128
#define GRPS 8
#define GBLK 16
#define JT   32
#define BT   8
// thread micro-tile: 4j x 8b x 16k, split-k = 32
#define HSTR 520            // h_sh row stride in floats (512 + 8 pad)
#define RSTR 37             // reduction row stride in floats

__device__ __align__(16) float g_hbuf[2 * BB * HH];
__device__ __align__(16) unsigned g_arrive[NBLK];   // zero-init; monotonic

// ---- f32x2 helpers -------------------------------------------------------
__device__ __forceinline__ unsigned long long pack2(float x, float y) {
    unsigned long long r;
    asm("mov.b64 %0, {%1, %2};" : "=l"(r) : "f"(x), "f"(y));
    return r;
}
__device__ __forceinline__ float hadd2(unsigned long long v) {
    float lo, hi;
    asm("mov.b64 {%0, %1}, %2;" : "=f"(lo), "=f"(hi) : "l"(v));
    return lo + hi;
}
#define FMA2(c, a, b) \
    asm("fma.rn.f32x2 %0, %1, %2, %3;" : "=l"(c) : "l"(a), "l"(b), "l"(c))

// ---------------------------------------------------------------------------
// Phase 1: xp = X @ W^T  (M=32768, N=512, K=512), 128x128 tile, 8x8 micro.
// ---------------------------------------------------------------------------
__global__ void __launch_bounds__(256) gemm_xp_kernel(
    const float* __restrict__ X, const float* __restrict__ W,
    float* __restrict__ C)
{
    const int K = II, N = HH;
    __shared__ __align__(16) float As[16][128];
    __shared__ __align__(16) float Bs[16][128];

    const int bm = blockIdx.x * 128;
    const int bn = blockIdx.y * 128;
    const int tid = threadIdx.x;
    const int tx = tid & 15;
    const int ty = tid >> 4;

    float acc[8][8];
#pragma unroll
    for (int i = 0; i < 8; i++)
#pragma unroll
        for (int j = 0; j < 8; j++) acc[i][j] = 0.0f;

    for (int k0 = 0; k0 < K; k0 += 16) {
#pragma unroll
        for (int l = 0; l < 2; l++) {
            int idx = tid + l * 256;
            int r = idx >> 2;
            int c = (idx & 3) * 4;
            float4 va = *(const float4*)&X[(size_t)(bm + r) * K + k0 + c];
            As[c + 0][r] = va.x; As[c + 1][r] = va.y;
            As[c + 2][r] = va.z; As[c + 3][r] = va.w;
            float4 vb = *(const float4*)&W[(size_t)(bn + r) * K + k0 + c];
            Bs[c + 0][r] = vb.x; Bs[c + 1][r] = vb.y;
            Bs[c + 2][r] = vb.z; Bs[c + 3][r] = vb.w;
        }
        __syncthreads();

#pragma unroll
        for (int kk = 0; kk < 16; kk++) {
            float a[8], b[8];
            *(float4*)&a[0] = *(const float4*)&As[kk][ty * 8];
            *(float4*)&a[4] = *(const float4*)&As[kk][ty * 8 + 4];
            *(float4*)&b[0] = *(const float4*)&Bs[kk][tx * 8];
            *(float4*)&b[4] = *(const float4*)&Bs[kk][tx * 8 + 4];
#pragma unroll
            for (int i = 0; i < 8; i++)
#pragma unroll
                for (int j = 0; j < 8; j++)
                    acc[i][j] = fmaf(a[i], b[j], acc[i][j]);
        }
        __syncthreads();
    }

#pragma unroll
    for (int i = 0; i < 8; i++) {
        int row = bm + ty * 8 + i;
        float4 v0 = make_float4(acc[i][0], acc[i][1], acc[i][2], acc[i][3]);
        float4 v1 = make_float4(acc[i][4], acc[i][5], acc[i][6], acc[i][7]);
        *(float4*)&C[(size_t)row * N + bn + tx * 8]     = v0;
        *(float4*)&C[(size_t)row * N + bn + tx * 8 + 4] = v1;
    }
}

// ---------------------------------------------------------------------------
// Phase 2: persistent recurrence, W in registers + f32x2 FMA + broadcast h.
//   bid = grp*16 + jt;  b0 = grp*8, j0 = jt*32.
//   tid = ks*8 + jp  (ks = tid>>3 in 0..31, jp = tid&7).
//   Thread owns W rows j0 + jp*4 + jj (jj 0..3), k in [ks*16, ks*16+16),
//   computes partial acc[4][8] (f32x2 over k-pairs) for 8 batches.
//   h_sh uses an XOR-4 swizzle on float4 slots (bit3 of k4 toggles bit2 of
//   the float offset) -> conflict-free LDS.128 reads.
//   Partials reduced via stride-37 smem; output thread o: j=o&31, b=o>>5.
// ---------------------------------------------------------------------------
__global__ void __launch_bounds__(256) rnn_recurrence_kernel(
    const float* __restrict__ w_hh, float* __restrict__ out, int has_last)
{
    extern __shared__ __align__(16) float smem[];
    float* h_sh = smem;                       // [BT][HSTR] = 8 x 520
    float* red  = smem + BT * HSTR;           // [256][RSTR] = 256 x 37

    const int tid = threadIdx.x;
    const int bid = blockIdx.x;
    const int grp = bid >> 4;
    const int jt  = bid & 15;
    const int b0  = grp * BT;
    const int j0  = jt * JT;

    const int ks = tid >> 3;       // 0..31
    const int jp = tid & 7;        // 0..7
    const int kbase = ks * 16;
    // XOR constant for this thread's k-slice: bit3 of k4 (= ks bit1) -> +-4
    const int cxor = (ks & 2) << 1;

    __shared__ unsigned s_base;
    if (tid == 0) s_base = *((volatile unsigned*)&g_arrive[bid]);

    // ---- load W slab into registers: wreg[jj][p] = (w[j][k2p], w[j][k2p+1])
    unsigned long long wreg[4][8];
#pragma unroll
    for (int jj = 0; jj < 4; jj++) {
        const float* wr = &w_hh[(size_t)(j0 + jp * 4 + jj) * HH + kbase];
#pragma unroll
        for (int q = 0; q < 4; q++) {
            float4 v = *(const float4*)&wr[q * 4];
            wreg[jj][q * 2 + 0] = pack2(v.x, v.y);
            wreg[jj][q * 2 + 1] = pack2(v.z, v.w);
        }
    }
    __syncthreads();
    const unsigned base = s_base;

    // output mapping (coalesced): j = o&31, b = o>>5
    const int gj = j0 + (tid & 31);
    const int gb = b0 + (tid >> 5);

    float* __restrict__ hall  = out;
    float* __restrict__ hlast = out + (size_t)TT * BB * HH;

    for (int t = 0; t < TT; t++) {
        // prefetch xp (own slice; no cross-block hazard)
        float xp = hall[((size_t)t * BB + gb) * HH + gj];

        float hsum = 0.0f;
        if (t > 0) {
            // ---- group barrier: wait for all 16 group blocks at step t-1
            if (tid < 32) {
                const unsigned tgt = base + (unsigned)t;
                const unsigned* fl = &g_arrive[grp * GBLK + (tid & 15)];
                for (;;) {
                    unsigned v = (tid < 16) ? __ldcg(fl) : tgt;
                    if (__all_sync(0xffffffffu, v >= tgt)) break;
                    __nanosleep(32);
                }
                __threadfence();
            }
            __syncthreads();

            // ---- stage h(t-1) slice [8 b][512 k] into h_sh (XOR swizzle)
            {
                const int prev = (t - 1) & 1;
                const float4* src = (const float4*)&g_hbuf[
                    (size_t)prev * BB * HH + (size_t)b0 * HH];
#pragma unroll
                for (int r = 0; r < 4; r++) {
                    int idx = tid + r * 256;       // 0..1023
                    int b  = idx >> 7;             // 0..7
                    int k4 = idx & 127;
                    float4 v = __ldcg(&src[(size_t)b * 128 + k4]);
                    int off = b * HSTR + ((k4 * 4) ^ (((k4 >> 3) & 1) << 2));
                    *(float4*)&h_sh[off] = v;
                }
            }
            __syncthreads();

            // ---- compute: acc[jj][bb] over 16 k (f32x2 pairs)
            unsigned long long acc[4][8];
#pragma unroll
            for (int jj = 0; jj < 4; jj++)
#pragma unroll
                for (int bb = 0; bb < 8; bb++) acc[jj][bb] = 0ULL;

#pragma unroll
            for (int q = 0; q < 4; q++) {        // 4 k per q
                const int koff = kbase + ((q * 4) ^ cxor);
#pragma unroll
                for (int bb = 0; bb < 8; bb++) {
                    ulonglong2 hv = *(const ulonglong2*)&h_sh[
                        bb * HSTR + koff];
#pragma unroll
                    for (int jj = 0; jj < 4; jj++) {
                        FMA2(acc[jj][bb], wreg[jj][q * 2 + 0], hv.x);
                        FMA2(acc[jj][bb], wreg[jj][q * 2 + 1], hv.y);
                    }
                }
            }

            // ---- partials -> red[row][ks], row = bb*32 + jp*4 + jj
#pragma unroll
            for (int jj = 0; jj < 4; jj++)
#pragma unroll
                for (int bb = 0; bb < 8; bb++)
                    red[(bb * 32 + jp * 4 + jj) * RSTR + ks] =
                        hadd2(acc[jj][bb]);
            __syncthreads();

            // ---- thread o sums its row (row index == o)
            const float* rr = &red[tid * RSTR];
            float s = 0.0f;
#pragma unroll
            for (int i = 0; i < 32; i++) s += rr[i];
            hsum = s;
        }

        float h = tanhf(xp + hsum);

        // state store first, then signal (hall store off critical path)
        g_hbuf[((size_t)(t & 1) * BB + gb) * HH + gj] = h;

        if (t != TT - 1) {
            __syncthreads();               // all g_hbuf stores issued; red free
            if (tid == 0) {
                __threadfence();
                *((volatile unsigned*)&g_arrive[bid]) = base + 1u + (unsigned)t;
            }
        }

        hall[((size_t)t * BB + gb) * HH + gj] = h;
        if (has_last && t == TT - 1)
            hlast[(size_t)gb * HH + gj] = h;
    }
}

// ---------------------------------------------------------------------------
extern "C" void kernel_launch(void* const* d_in, const int* in_sizes, int n_in,
                              void* d_out, int out_size) {
    const float* x    = (const float*)d_in[0];   // (T, B, I)
    const float* w_ih = (const float*)d_in[1];   // (H, I)
    const float* w_hh = (const float*)d_in[2];   // (H, H)
    float* out = (float*)d_out;

    dim3 g1((TT * BB) / 128, HH / 128);
    gemm_xp_kernel<<<g1, 256>>>(x, w_ih, out);

    int smem_bytes = (BT * HSTR + 256 * RSTR) * (int)sizeof(float); // ~54KB
    cudaFuncSetAttribute(rnn_recurrence_kernel,
                         cudaFuncAttributeMaxDynamicSharedMemorySize, smem_bytes);
    int has_last = (out_size >= TT * BB * HH + BB * HH) ? 1 : 0;
    rnn_recurrence_kernel<<<NBLK, 256, smem_bytes>>>(w_hh, out, has_last);
}